// round 2
// baseline (speedup 1.0000x reference)
#include <cuda_runtime.h>
#include <math.h>

#define BSZ   4096
#define NROWS 8192
#define DDIM  256
#define EPSF      1e-8f
#define COS_EPSF  1e-8f
#define INV_SQRT_TAU 1.4142135623730951f   // 1/sqrt(0.5)

#define BM 64
#define BN 64
#define BKK 32

// Scratch (no device allocation allowed)
__device__ float g_zn[NROWS * DDIM];   // normalized rows * 1/sqrt(tau), 8 MB
__device__ float g_negsum[NROWS];
__device__ float g_spos[NROWS];

// ---------------------------------------------------------------------------
// Kernel 1: row-normalize z = [zi; zj], fold in 1/sqrt(tau); zero negsum.
// One block per row, 64 threads, float4 per thread.
// ---------------------------------------------------------------------------
__global__ __launch_bounds__(64) void normalize_kernel(
    const float* __restrict__ zi, const float* __restrict__ zj)
{
    int row = blockIdx.x;
    int t = threadIdx.x;
    const float* src = (row < BSZ) ? (zi + (size_t)row * DDIM)
                                   : (zj + (size_t)(row - BSZ) * DDIM);
    float4 v = ((const float4*)src)[t];
    float ss = v.x * v.x + v.y * v.y + v.z * v.z + v.w * v.w;
    #pragma unroll
    for (int o = 16; o; o >>= 1) ss += __shfl_down_sync(0xffffffffu, ss, o);
    __shared__ float sh[2];
    if ((t & 31) == 0) sh[t >> 5] = ss;
    __syncthreads();
    float total = sh[0] + sh[1];
    float scale = INV_SQRT_TAU / fmaxf(sqrtf(total), COS_EPSF);
    v.x *= scale; v.y *= scale; v.z *= scale; v.w *= scale;
    ((float4*)(g_zn + (size_t)row * DDIM))[t] = v;
    if (t == 0) g_negsum[row] = 0.0f;
}

// ---------------------------------------------------------------------------
// Kernel 2: tiled GEMM zn @ zn^T with fused exp/row-sum/positive-capture
// epilogue. BM=BN=64, BK=32, 256 threads (16x16), each thread owns a 4x4
// micro-tile. Smem tiles stored [k][row] so fragment reads are float4 and
// conflict-free (A reads broadcast across ty, B reads stride across tx).
// ---------------------------------------------------------------------------
__global__ __launch_bounds__(256) void sim_kernel()
{
    __shared__ float As[BKK][BM];
    __shared__ float Bs[BKK][BN];

    int tid = threadIdx.x;
    int tx = tid & 15;
    int ty = tid >> 4;
    int i0 = blockIdx.y * BM;
    int j0 = blockIdx.x * BN;

    float acc[4][4] = {};

    for (int k0 = 0; k0 < DDIM; k0 += BKK) {
        // Load 64x32 A-tile and B-tile, transposing into [k][row].
        #pragma unroll
        for (int p = 0; p < 2; p++) {
            int f  = tid + p * 256;   // float4 index: 512 per tile
            int r  = f >> 3;          // row within tile (0..63)
            int c4 = f & 7;           // float4 along k (0..7)
            float4 va = *(const float4*)(g_zn + (size_t)(i0 + r) * DDIM + k0 + c4 * 4);
            As[c4 * 4 + 0][r] = va.x; As[c4 * 4 + 1][r] = va.y;
            As[c4 * 4 + 2][r] = va.z; As[c4 * 4 + 3][r] = va.w;
            float4 vb = *(const float4*)(g_zn + (size_t)(j0 + r) * DDIM + k0 + c4 * 4);
            Bs[c4 * 4 + 0][r] = vb.x; Bs[c4 * 4 + 1][r] = vb.y;
            Bs[c4 * 4 + 2][r] = vb.z; Bs[c4 * 4 + 3][r] = vb.w;
        }
        __syncthreads();

        #pragma unroll
        for (int k = 0; k < BKK; k++) {
            float4 a = *(const float4*)&As[k][ty * 4];
            float4 b = *(const float4*)&Bs[k][tx * 4];
            float av[4] = {a.x, a.y, a.z, a.w};
            float bv[4] = {b.x, b.y, b.z, b.w};
            #pragma unroll
            for (int ri = 0; ri < 4; ri++)
                #pragma unroll
                for (int ci = 0; ci < 4; ci++)
                    acc[ri][ci] = fmaf(av[ri], bv[ci], acc[ri][ci]);
        }
        __syncthreads();
    }

    // Epilogue: exp, diagonal exclusion, positive capture, row-sum reduce.
    #pragma unroll
    for (int ri = 0; ri < 4; ri++) {
        int gi = i0 + ty * 4 + ri;
        int gpair = (gi < BSZ) ? (gi + BSZ) : (gi - BSZ);
        float rsum = 0.0f;
        #pragma unroll
        for (int ci = 0; ci < 4; ci++) {
            int gj = j0 + tx * 4 + ci;
            float s = acc[ri][ci];
            float e = __expf(s);
            if (gj == gi) e = 0.0f;        // exclude diagonal
            if (gj == gpair) g_spos[gi] = s; // unique writer per row
            rsum += e;
        }
        // reduce across the 16 tx lanes (two independent 16-groups per warp)
        #pragma unroll
        for (int o = 8; o; o >>= 1)
            rsum += __shfl_down_sync(0xffffffffu, rsum, o, 16);
        if (tx == 0) atomicAdd(&g_negsum[gi], rsum);
    }
}

// ---------------------------------------------------------------------------
// Kernel 3: loss = mean( log(negsum + eps) - s_pos )
// ---------------------------------------------------------------------------
__global__ __launch_bounds__(256) void loss_kernel(float* __restrict__ out)
{
    __shared__ float sh[256];
    int t = threadIdx.x;
    float acc = 0.0f;
    for (int i = t; i < NROWS; i += 256)
        acc += logf(g_negsum[i] + EPSF) - g_spos[i];
    sh[t] = acc;
    __syncthreads();
    #pragma unroll
    for (int o = 128; o; o >>= 1) {
        if (t < o) sh[t] += sh[t + o];
        __syncthreads();
    }
    if (t == 0) out[0] = sh[0] / (float)NROWS;
}

// ---------------------------------------------------------------------------
extern "C" void kernel_launch(void* const* d_in, const int* in_sizes, int n_in,
                              void* d_out, int out_size)
{
    const float* zi = (const float*)d_in[0];
    const float* zj = (const float*)d_in[1];
    float* out = (float*)d_out;

    normalize_kernel<<<NROWS, 64>>>(zi, zj);
    dim3 grid(NROWS / BN, NROWS / BM);
    sim_kernel<<<grid, 256>>>();
    loss_kernel<<<1, 256>>>(out);
}

// round 4
// speedup vs baseline: 14.3509x; 14.3509x over previous
#include <cuda_runtime.h>
#include <cuda_bf16.h>
#include <cstdint>
#include <math.h>

#define BSZ   4096
#define NROWS 8192
#define DDIM  256
#define EPSF      1e-8f
#define COS_EPSF  1e-8f
#define INV_SQRT_TAU 1.4142135623730951f   // 1/sqrt(0.5)

#define TILE 128
#define BK   128                 // k-chunk held in smem (2 chunks total)
#define SMEM_BYTES (2 * TILE * BK * 2)   // A + B chunk, bf16: 65536

// Scratch (device globals; no allocation allowed)
__device__ __nv_bfloat16 g_zn[NROWS * DDIM];   // normalized * 1/sqrt(tau)
__device__ float g_negsum[NROWS];
__device__ float g_spos[NROWS];

__device__ __forceinline__ uint32_t smem_u32(const void* p) {
    uint32_t a;
    asm("{ .reg .u64 t; cvta.to.shared.u64 t, %1; cvt.u32.u64 %0, t; }"
        : "=r"(a) : "l"(p));
    return a;
}

#define LDSM_X4(r, a) \
    asm volatile("ldmatrix.sync.aligned.m8n8.x4.shared.b16 {%0,%1,%2,%3}, [%4];" \
        : "=r"((r)[0]), "=r"((r)[1]), "=r"((r)[2]), "=r"((r)[3]) : "r"(a))

#define MMA16816(d, a, b0, b1) \
    asm volatile("mma.sync.aligned.m16n8k16.row.col.f32.bf16.bf16.f32 " \
        "{%0,%1,%2,%3}, {%4,%5,%6,%7}, {%8,%9}, {%0,%1,%2,%3};" \
        : "+f"((d)[0]), "+f"((d)[1]), "+f"((d)[2]), "+f"((d)[3]) \
        : "r"((a)[0]), "r"((a)[1]), "r"((a)[2]), "r"((a)[3]), "r"(b0), "r"(b1))

// ---------------------------------------------------------------------------
// Kernel 1: row-normalize [zi; zj], fold in 1/sqrt(tau), emit bf16; zero negsum.
// ---------------------------------------------------------------------------
__global__ __launch_bounds__(64) void normalize_kernel(
    const float* __restrict__ zi, const float* __restrict__ zj)
{
    int row = blockIdx.x;
    int t = threadIdx.x;
    const float* src = (row < BSZ) ? (zi + (size_t)row * DDIM)
                                   : (zj + (size_t)(row - BSZ) * DDIM);
    float4 v = ((const float4*)src)[t];
    float ss = v.x * v.x + v.y * v.y + v.z * v.z + v.w * v.w;
    #pragma unroll
    for (int o = 16; o; o >>= 1) ss += __shfl_down_sync(0xffffffffu, ss, o);
    __shared__ float sh[2];
    if ((t & 31) == 0) sh[t >> 5] = ss;
    __syncthreads();
    float total = sh[0] + sh[1];
    float scale = INV_SQRT_TAU / fmaxf(sqrtf(total), COS_EPSF);
    __nv_bfloat162* dst = (__nv_bfloat162*)(g_zn + (size_t)row * DDIM);
    dst[2 * t + 0] = __nv_bfloat162(__float2bfloat16(v.x * scale), __float2bfloat16(v.y * scale));
    dst[2 * t + 1] = __nv_bfloat162(__float2bfloat16(v.z * scale), __float2bfloat16(v.w * scale));
    if (t == 0) g_negsum[row] = 0.0f;
}

// ---------------------------------------------------------------------------
// Kernel 2: HMMA 128x128 tile of sim = zn @ zn^T, upper-triangle tiles only.
// 8 warps in 4x2; each warp computes 32x64 via m16n8k16 bf16 mma.sync.
// Epilogue: exp + diag-exclusion + pos-capture + row sums; off-diag tiles
// additionally emit column sums (transpose contribution) — symmetry halves
// the GEMM work.
// Smem layout per tile chunk: row r (0..127), 16B chunk c (0..15):
//   off = r*256 + ((c ^ (r&7)) << 4)   -> conflict-free ldmatrix.
// ---------------------------------------------------------------------------
__global__ __launch_bounds__(256, 2) void sim_kernel()
{
    int bi = blockIdx.y, bj = blockIdx.x;
    if (bj < bi) return;                      // symmetry: upper triangle only
    extern __shared__ char smem[];
    int i0 = bi * TILE, j0 = bj * TILE;
    int tid = threadIdx.x, wid = tid >> 5, l = tid & 31;
    int r0 = (wid >> 1) * 32;                 // warp row offset (4 warps)
    int n0 = (wid & 1) * 64;                  // warp col offset (2 warps)
    uint32_t sA = smem_u32(smem);
    uint32_t sB = sA + 32768;

    float acc[2][8][4] = {};

    // ldmatrix lane addressing (see fragment layout notes)
    int a_row = l & 15;                       // + mt*16 + r0
    int a_hi  = l >> 4;                       // k-chunk select
    int b_row = (l & 7) + ((l >> 4) << 3);    // + np*16 + n0
    int b_hi  = (l >> 3) & 1;

    const uint4* gz = (const uint4*)g_zn;     // 32 uint4 per 256-elem row

    #pragma unroll
    for (int kc = 0; kc < 2; kc++) {
        if (kc) __syncthreads();              // finish reads before overwrite
        #pragma unroll
        for (int it = 0; it < 8; it++) {
            int f = tid + it * 256;           // 0..2047 per tile
            int r = f >> 4, c = f & 15;
            uint32_t off = (uint32_t)(r * 256 + ((c ^ (r & 7)) << 4));
            *(uint4*)(smem + off)         = gz[(size_t)(i0 + r) * 32 + kc * 16 + c];
            *(uint4*)(smem + 32768 + off) = gz[(size_t)(j0 + r) * 32 + kc * 16 + c];
        }
        __syncthreads();

        #pragma unroll
        for (int ks = 0; ks < 8; ks++) {
            uint32_t af[2][4], bf[4][4];
            #pragma unroll
            for (int mt = 0; mt < 2; mt++) {
                int row = r0 + mt * 16 + a_row;
                LDSM_X4(af[mt], sA + row * 256 + (((2 * ks + a_hi) ^ (row & 7)) << 4));
            }
            #pragma unroll
            for (int np = 0; np < 4; np++) {
                int row = n0 + np * 16 + b_row;
                LDSM_X4(bf[np], sB + row * 256 + (((2 * ks + b_hi) ^ (row & 7)) << 4));
            }
            #pragma unroll
            for (int mt = 0; mt < 2; mt++)
                #pragma unroll
                for (int np = 0; np < 4; np++) {
                    MMA16816(acc[mt][2 * np + 0], af[mt], bf[np][0], bf[np][1]);
                    MMA16816(acc[mt][2 * np + 1], af[mt], bf[np][2], bf[np][3]);
                }
        }
    }

    // ---- epilogue ----
    int gid = l >> 2, t4 = l & 3;
    bool offd = (bj != bi);
    float cs0[8] = {}, cs1[8] = {};           // column partial sums

    #pragma unroll
    for (int mt = 0; mt < 2; mt++) {
        int ra = i0 + r0 + mt * 16 + gid;
        int rb = ra + 8;
        int pa = (ra < BSZ) ? ra + BSZ : ra - BSZ;
        int pb = (rb < BSZ) ? rb + BSZ : rb - BSZ;
        float rsa = 0.0f, rsb = 0.0f;
        #pragma unroll
        for (int nt = 0; nt < 8; nt++) {
            int col = j0 + n0 + nt * 8 + 2 * t4;
            float s0 = acc[mt][nt][0], s1 = acc[mt][nt][1];
            float s2 = acc[mt][nt][2], s3 = acc[mt][nt][3];
            // positive-pair capture: pair offset is BSZ -> always off-diag tile;
            // symmetric value serves both rows, each written exactly once chip-wide.
            if (col == pa)     { g_spos[ra] = s0; g_spos[col] = s0; }
            if (col + 1 == pa) { g_spos[ra] = s1; g_spos[col + 1] = s1; }
            if (col == pb)     { g_spos[rb] = s2; g_spos[col] = s2; }
            if (col + 1 == pb) { g_spos[rb] = s3; g_spos[col + 1] = s3; }
            float e0 = (col == ra)     ? 0.0f : __expf(s0);
            float e1 = (col + 1 == ra) ? 0.0f : __expf(s1);
            float e2 = (col == rb)     ? 0.0f : __expf(s2);
            float e3 = (col + 1 == rb) ? 0.0f : __expf(s3);
            rsa += e0 + e1; rsb += e2 + e3;
            cs0[nt] += e0 + e2; cs1[nt] += e1 + e3;
        }
        // reduce over the 4 lanes sharing this row (t4 = 0..3)
        rsa += __shfl_xor_sync(0xffffffffu, rsa, 1);
        rsa += __shfl_xor_sync(0xffffffffu, rsa, 2);
        rsb += __shfl_xor_sync(0xffffffffu, rsb, 1);
        rsb += __shfl_xor_sync(0xffffffffu, rsb, 2);
        if (t4 == 0) {
            atomicAdd(&g_negsum[ra], rsa);
            atomicAdd(&g_negsum[rb], rsb);
        }
    }

    if (offd) {
        // transpose contribution: column sums -> rows of the j-block
        #pragma unroll
        for (int nt = 0; nt < 8; nt++) {
            float c0 = cs0[nt], c1 = cs1[nt];
            c0 += __shfl_xor_sync(0xffffffffu, c0, 4);
            c0 += __shfl_xor_sync(0xffffffffu, c0, 8);
            c0 += __shfl_xor_sync(0xffffffffu, c0, 16);
            c1 += __shfl_xor_sync(0xffffffffu, c1, 4);
            c1 += __shfl_xor_sync(0xffffffffu, c1, 8);
            c1 += __shfl_xor_sync(0xffffffffu, c1, 16);
            if (gid == 0) {
                int col = j0 + n0 + nt * 8 + 2 * t4;
                atomicAdd(&g_negsum[col], c0);
                atomicAdd(&g_negsum[col + 1], c1);
            }
        }
    }
}

// ---------------------------------------------------------------------------
// Kernel 3: loss = mean( log(negsum + eps) - s_pos )
// ---------------------------------------------------------------------------
__global__ __launch_bounds__(256) void loss_kernel(float* __restrict__ out)
{
    __shared__ float sh[256];
    int t = threadIdx.x;
    float acc = 0.0f;
    for (int i = t; i < NROWS; i += 256)
        acc += logf(g_negsum[i] + EPSF) - g_spos[i];
    sh[t] = acc;
    __syncthreads();
    #pragma unroll
    for (int o = 128; o; o >>= 1) {
        if (t < o) sh[t] += sh[t + o];
        __syncthreads();
    }
    if (t == 0) out[0] = sh[0] / (float)NROWS;
}

// ---------------------------------------------------------------------------
extern "C" void kernel_launch(void* const* d_in, const int* in_sizes, int n_in,
                              void* d_out, int out_size)
{
    const float* zi = (const float*)d_in[0];
    const float* zj = (const float*)d_in[1];
    float* out = (float*)d_out;

    static int inited = 0;
    if (!inited) {   // attribute set is idempotent host-side config, not work
        cudaFuncSetAttribute(sim_kernel,
                             cudaFuncAttributeMaxDynamicSharedMemorySize,
                             SMEM_BYTES);
        inited = 1;
    }

    normalize_kernel<<<NROWS, 64>>>(zi, zj);
    dim3 grid(NROWS / TILE, NROWS / TILE);    // 64 x 64, lower triangle exits
    sim_kernel<<<grid, 256, SMEM_BYTES>>>();
    loss_kernel<<<1, 256>>>(out);
}

// round 5
// speedup vs baseline: 19.3031x; 1.3451x over previous
#include <cuda_runtime.h>
#include <cuda_bf16.h>
#include <cstdint>
#include <math.h>

#define BSZ   4096
#define NROWS 8192
#define DDIM  256
#define EPSF      1e-8f
#define COS_EPSF  1e-8f
#define INV_SQRT_TAU 1.4142135623730951f   // 1/sqrt(0.5)

#define TILE 128
#define BK   64                            // k per pipeline stage (128 B/row)
#define STAGE_BYTES (TILE * 128)           // 16 KB per operand per stage
#define SMEM_BYTES (4 * STAGE_BYTES)       // A0,B0,A1,B1 = 64 KB

// Scratch (device globals; no allocation allowed)
__device__ __nv_bfloat16 g_zn[NROWS * DDIM];   // normalized * 1/sqrt(tau)
__device__ float g_negsum[NROWS];
__device__ float g_spos[NROWS];

__device__ __forceinline__ uint32_t smem_u32(const void* p) {
    uint32_t a;
    asm("{ .reg .u64 t; cvta.to.shared.u64 t, %1; cvt.u32.u64 %0, t; }"
        : "=r"(a) : "l"(p));
    return a;
}

__device__ __forceinline__ void cp16(uint32_t dst, const void* src) {
    asm volatile("cp.async.cg.shared.global [%0], [%1], 16;"
                 :: "r"(dst), "l"(src) : "memory");
}
#define CP_COMMIT() asm volatile("cp.async.commit_group;" ::: "memory")
#define CP_WAIT0()  asm volatile("cp.async.wait_group 0;" ::: "memory")

#define LDSM_X4(r, a) \
    asm volatile("ldmatrix.sync.aligned.m8n8.x4.shared.b16 {%0,%1,%2,%3}, [%4];" \
        : "=r"((r)[0]), "=r"((r)[1]), "=r"((r)[2]), "=r"((r)[3]) : "r"(a))

#define MMA16816(d, a, b0, b1) \
    asm volatile("mma.sync.aligned.m16n8k16.row.col.f32.bf16.bf16.f32 " \
        "{%0,%1,%2,%3}, {%4,%5,%6,%7}, {%8,%9}, {%0,%1,%2,%3};" \
        : "+f"((d)[0]), "+f"((d)[1]), "+f"((d)[2]), "+f"((d)[3]) \
        : "r"((a)[0]), "r"((a)[1]), "r"((a)[2]), "r"((a)[3]), "r"(b0), "r"(b1))

// ---------------------------------------------------------------------------
// Kernel 1: row-normalize [zi; zj], fold in 1/sqrt(tau), emit bf16.
// One warp per row, no smem, no block barriers.
// ---------------------------------------------------------------------------
__global__ __launch_bounds__(256) void normalize_kernel(
    const float* __restrict__ zi, const float* __restrict__ zj)
{
    int row = blockIdx.x * 8 + (threadIdx.x >> 5);
    int l = threadIdx.x & 31;
    const float* src = (row < BSZ) ? (zi + (size_t)row * DDIM)
                                   : (zj + (size_t)(row - BSZ) * DDIM);
    float4 v0 = ((const float4*)src)[l];
    float4 v1 = ((const float4*)src)[l + 32];
    float ss = v0.x * v0.x + v0.y * v0.y + v0.z * v0.z + v0.w * v0.w
             + v1.x * v1.x + v1.y * v1.y + v1.z * v1.z + v1.w * v1.w;
    #pragma unroll
    for (int o = 16; o; o >>= 1) ss += __shfl_xor_sync(0xffffffffu, ss, o);
    float scale = INV_SQRT_TAU / fmaxf(sqrtf(ss), COS_EPSF);
    __nv_bfloat162* dst = (__nv_bfloat162*)(g_zn + (size_t)row * DDIM);
    dst[2 * l + 0]  = __nv_bfloat162(__float2bfloat16(v0.x * scale), __float2bfloat16(v0.y * scale));
    dst[2 * l + 1]  = __nv_bfloat162(__float2bfloat16(v0.z * scale), __float2bfloat16(v0.w * scale));
    dst[64 + 2 * l] = __nv_bfloat162(__float2bfloat16(v1.x * scale), __float2bfloat16(v1.y * scale));
    dst[65 + 2 * l] = __nv_bfloat162(__float2bfloat16(v1.z * scale), __float2bfloat16(v1.w * scale));
    if (l == 0) g_negsum[row] = 0.0f;
}

// ---------------------------------------------------------------------------
// Kernel 2: HMMA 128x128 tile of sim = zn @ zn^T, upper-triangle tiles only,
// cp.async double-buffered over 4 k-stages of BK=64.
// 8 warps in 4x2; each warp computes 32x64 via m16n8k16 bf16 mma.sync.
// Stage layout: row r (0..127) * 128B, 16B chunk c (0..7), SW128 swizzle.
// ---------------------------------------------------------------------------
__global__ __launch_bounds__(256, 2) void sim_kernel()
{
    int bi = blockIdx.y, bj = blockIdx.x;
    if (bj < bi) return;                      // symmetry: upper triangle only
    extern __shared__ char smem[];
    int i0 = bi * TILE, j0 = bj * TILE;
    int tid = threadIdx.x, wid = tid >> 5, l = tid & 31;
    int r0 = (wid >> 1) * 32;                 // warp row offset (4 warps)
    int n0 = (wid & 1) * 64;                  // warp col offset (2 warps)
    uint32_t sbase = smem_u32(smem);

    float acc[2][8][4] = {};

    // ldmatrix lane addressing
    int a_row = l & 15, a_hi = l >> 4;
    int b_row = (l & 7) + ((l >> 4) << 3), b_hi = (l >> 3) & 1;

    const uint4* gz = (const uint4*)g_zn;     // 32 uint4 per 256-elem row

    // per-thread load coords (4 x 16B per operand per stage)
    int lr[4], lc[4]; uint32_t loff[4];
    #pragma unroll
    for (int it = 0; it < 4; it++) {
        int f = tid + it * 256;               // 0..1023
        lr[it] = f >> 3; lc[it] = f & 7;
        loff[it] = (uint32_t)(lr[it] * 128 + ((lc[it] ^ (lr[it] & 7)) << 4));
    }

    // prologue: stage 0 into buffer 0
    #pragma unroll
    for (int it = 0; it < 4; it++) {
        cp16(sbase + loff[it],               &gz[(size_t)(i0 + lr[it]) * 32 + lc[it]]);
        cp16(sbase + STAGE_BYTES + loff[it], &gz[(size_t)(j0 + lr[it]) * 32 + lc[it]]);
    }
    CP_COMMIT();

    #pragma unroll
    for (int kc = 0; kc < 4; kc++) {
        int s = kc & 1;
        CP_WAIT0();
        __syncthreads();
        if (kc < 3) {                         // prefetch next stage
            uint32_t nb = sbase + (uint32_t)((s ^ 1) * 2 * STAGE_BYTES);
            #pragma unroll
            for (int it = 0; it < 4; it++) {
                cp16(nb + loff[it],               &gz[(size_t)(i0 + lr[it]) * 32 + (kc + 1) * 8 + lc[it]]);
                cp16(nb + STAGE_BYTES + loff[it], &gz[(size_t)(j0 + lr[it]) * 32 + (kc + 1) * 8 + lc[it]]);
            }
            CP_COMMIT();
        }
        uint32_t sA = sbase + (uint32_t)(s * 2 * STAGE_BYTES);
        uint32_t sB = sA + STAGE_BYTES;

        #pragma unroll
        for (int ks = 0; ks < 4; ks++) {
            uint32_t af[2][4], bf[4][4];
            #pragma unroll
            for (int mt = 0; mt < 2; mt++) {
                int row = r0 + mt * 16 + a_row;
                LDSM_X4(af[mt], sA + row * 128 + (((2 * ks + a_hi) ^ (row & 7)) << 4));
            }
            #pragma unroll
            for (int np = 0; np < 4; np++) {
                int row = n0 + np * 16 + b_row;
                LDSM_X4(bf[np], sB + row * 128 + (((2 * ks + b_hi) ^ (row & 7)) << 4));
            }
            #pragma unroll
            for (int mt = 0; mt < 2; mt++)
                #pragma unroll
                for (int np = 0; np < 4; np++) {
                    MMA16816(acc[mt][2 * np + 0], af[mt], bf[np][0], bf[np][1]);
                    MMA16816(acc[mt][2 * np + 1], af[mt], bf[np][2], bf[np][3]);
                }
        }
        __syncthreads();                      // reads done before overwrite
    }

    // ---- epilogue ----
    int gid = l >> 2, t4 = l & 3;
    bool offd = (bj != bi);
    float cs0[8] = {}, cs1[8] = {};           // column partial sums

    #pragma unroll
    for (int mt = 0; mt < 2; mt++) {
        int ra = i0 + r0 + mt * 16 + gid;
        int rb = ra + 8;
        int pa = (ra < BSZ) ? ra + BSZ : ra - BSZ;
        int pb = (rb < BSZ) ? rb + BSZ : rb - BSZ;
        float rsa = 0.0f, rsb = 0.0f;
        #pragma unroll
        for (int nt = 0; nt < 8; nt++) {
            int col = j0 + n0 + nt * 8 + 2 * t4;
            float s0 = acc[mt][nt][0], s1 = acc[mt][nt][1];
            float s2 = acc[mt][nt][2], s3 = acc[mt][nt][3];
            // positive-pair capture: pair offset = BSZ -> always off-diag tile;
            // symmetric value serves both rows, each written once chip-wide.
            if (col == pa)     { g_spos[ra] = s0; g_spos[col] = s0; }
            if (col + 1 == pa) { g_spos[ra] = s1; g_spos[col + 1] = s1; }
            if (col == pb)     { g_spos[rb] = s2; g_spos[col] = s2; }
            if (col + 1 == pb) { g_spos[rb] = s3; g_spos[col + 1] = s3; }
            float e0 = (col == ra)     ? 0.0f : __expf(s0);
            float e1 = (col + 1 == ra) ? 0.0f : __expf(s1);
            float e2 = (col == rb)     ? 0.0f : __expf(s2);
            float e3 = (col + 1 == rb) ? 0.0f : __expf(s3);
            rsa += e0 + e1; rsb += e2 + e3;
            cs0[nt] += e0 + e2; cs1[nt] += e1 + e3;
        }
        rsa += __shfl_xor_sync(0xffffffffu, rsa, 1);
        rsa += __shfl_xor_sync(0xffffffffu, rsa, 2);
        rsb += __shfl_xor_sync(0xffffffffu, rsb, 1);
        rsb += __shfl_xor_sync(0xffffffffu, rsb, 2);
        if (t4 == 0) {
            atomicAdd(&g_negsum[ra], rsa);
            atomicAdd(&g_negsum[rb], rsb);
        }
    }

    if (offd) {
        // transpose contribution: column sums -> rows of the j-block
        #pragma unroll
        for (int nt = 0; nt < 8; nt++) {
            float c0 = cs0[nt], c1 = cs1[nt];
            c0 += __shfl_xor_sync(0xffffffffu, c0, 4);
            c0 += __shfl_xor_sync(0xffffffffu, c0, 8);
            c0 += __shfl_xor_sync(0xffffffffu, c0, 16);
            c1 += __shfl_xor_sync(0xffffffffu, c1, 4);
            c1 += __shfl_xor_sync(0xffffffffu, c1, 8);
            c1 += __shfl_xor_sync(0xffffffffu, c1, 16);
            if (gid == 0) {
                int col = j0 + n0 + nt * 8 + 2 * t4;
                atomicAdd(&g_negsum[col], c0);
                atomicAdd(&g_negsum[col + 1], c1);
            }
        }
    }
}

// ---------------------------------------------------------------------------
// Kernel 3: loss = mean( log(negsum + eps) - s_pos )
// ---------------------------------------------------------------------------
__global__ __launch_bounds__(256) void loss_kernel(float* __restrict__ out)
{
    __shared__ float sh[256];
    int t = threadIdx.x;
    float acc = 0.0f;
    for (int i = t; i < NROWS; i += 256)
        acc += __logf(g_negsum[i] + EPSF) - g_spos[i];
    sh[t] = acc;
    __syncthreads();
    #pragma unroll
    for (int o = 128; o; o >>= 1) {
        if (t < o) sh[t] += sh[t + o];
        __syncthreads();
    }
    if (t == 0) out[0] = sh[0] / (float)NROWS;
}

// ---------------------------------------------------------------------------
extern "C" void kernel_launch(void* const* d_in, const int* in_sizes, int n_in,
                              void* d_out, int out_size)
{
    const float* zi = (const float*)d_in[0];
    const float* zj = (const float*)d_in[1];
    float* out = (float*)d_out;

    static int inited = 0;
    if (!inited) {
        cudaFuncSetAttribute(sim_kernel,
                             cudaFuncAttributeMaxDynamicSharedMemorySize,
                             SMEM_BYTES);
        inited = 1;
    }

    normalize_kernel<<<NROWS / 8, 256>>>(zi, zj);
    dim3 grid(NROWS / TILE, NROWS / TILE);    // 64 x 64, lower triangle exits
    sim_kernel<<<grid, 256, SMEM_BYTES>>>();
    loss_kernel<<<1, 256>>>(out);
}